// round 12
// baseline (speedup 1.0000x reference)
#include <cuda_runtime.h>
#include <math.h>

#define B_ 4
#define S_ 4096
#define H_ 2048
#define E_ 16
#define ED_ 512

#define BAR_SYNC(id, cnt) asm volatile("bar.sync %0, %1;" :: "r"(id), "r"(cnt) : "memory")

// ---------------- scratch ----------------
// Zero-invariant protocol (deterministic under graph replay):
//   g_q/g_k : zeroed at head of k_ln_mean (before k_gemv accumulates)
//   g_acc   : zeroed at head of k_att (after k_gemv, its only reader, is done;
//             before next call's k_ln_mean accumulates)
__device__ float g_acc[B_ * H_];   // sum_s (x-mu)*rstd
__device__ float g_q[B_ * H_];     // bias added by c==0 gemv blocks
__device__ float g_k[E_ * H_];
__device__ float g_att[B_ * E_];   // overwritten every call
__device__ float g_eb[E_];         // overwritten every call

// ---------------- K1: fused LayerNorm + mean over S ----------------
// grid 256 = 4 batches * 64 blocks; 256 threads = 8 warps = 4 warp-pairs.
// A warp-pair owns a row: each warp covers 1024 columns (8 float4/lane).
// Pairs synchronize ONLY with each other via named barriers (id = pair+1).
// Row loop ping-pong unrolled x2 (prefetch next row while reducing current).
__global__ void __launch_bounds__(256, 2) k_ln_mean(const float* __restrict__ x) {
    // zero g_q (2048 float4) + g_k (8192 float4): blocks 0..39, 1 store/thread
    if (blockIdx.x < 40) {
        int i = blockIdx.x * 256 + threadIdx.x;
        float4 z = make_float4(0.f, 0.f, 0.f, 0.f);
        if (i < 2048) ((float4*)g_q)[i] = z;
        else          ((float4*)g_k)[i - 2048] = z;
    }

    int b   = blockIdx.x >> 6;      // 64 blocks per batch
    int blk = blockIdx.x & 63;
    int tid = threadIdx.x;
    int lane = tid & 31, wid = tid >> 5;
    int pair = wid >> 1, half = wid & 1;
    int barid = pair + 1;

    int row0 = blk * 64 + pair * 16;    // this pair's first row
    const float* xb = x + ((size_t)b * S_ + row0) * H_ + half * 1024;

    __shared__ float2 st[2][4][2];      // [buf][pair][half]
    __shared__ float sm[H_];

    float4 v[8], vn[8], acc[8];
    #pragma unroll
    for (int k = 0; k < 8; k++) acc[k] = make_float4(0.f, 0.f, 0.f, 0.f);

    {
        const float4* row = (const float4*)xb;
        #pragma unroll
        for (int k = 0; k < 8; k++) v[k] = __ldcs(&row[k * 32 + lane]);
    }

    for (int r = 0; r < 16; r += 2) {
        {
            const float4* nr = (const float4*)(xb + (size_t)(r + 1) * H_);
            #pragma unroll
            for (int k = 0; k < 8; k++) vn[k] = __ldcs(&nr[k * 32 + lane]);
        }
        {
            float s = 0.f, ss = 0.f;
            #pragma unroll
            for (int k = 0; k < 8; k++) {
                s  += v[k].x + v[k].y + v[k].z + v[k].w;
                ss += v[k].x * v[k].x + v[k].y * v[k].y
                    + v[k].z * v[k].z + v[k].w * v[k].w;
            }
            #pragma unroll
            for (int o = 16; o; o >>= 1) {
                s  += __shfl_xor_sync(0xffffffffu, s, o);
                ss += __shfl_xor_sync(0xffffffffu, ss, o);
            }
            if (lane == 0) st[0][pair][half] = make_float2(s, ss);
            BAR_SYNC(barid, 64);
            float2 oth = st[0][pair][half ^ 1];
            s += oth.x; ss += oth.y;
            float mu   = s * (1.0f / (float)H_);
            float rstd = rsqrtf(ss * (1.0f / (float)H_) - mu * mu + 1e-5f);
            #pragma unroll
            for (int k = 0; k < 8; k++) {
                acc[k].x += (v[k].x - mu) * rstd;
                acc[k].y += (v[k].y - mu) * rstd;
                acc[k].z += (v[k].z - mu) * rstd;
                acc[k].w += (v[k].w - mu) * rstd;
            }
        }
        if (r + 2 < 16) {
            const float4* nr = (const float4*)(xb + (size_t)(r + 2) * H_);
            #pragma unroll
            for (int k = 0; k < 8; k++) v[k] = __ldcs(&nr[k * 32 + lane]);
        }
        {
            float s = 0.f, ss = 0.f;
            #pragma unroll
            for (int k = 0; k < 8; k++) {
                s  += vn[k].x + vn[k].y + vn[k].z + vn[k].w;
                ss += vn[k].x * vn[k].x + vn[k].y * vn[k].y
                    + vn[k].z * vn[k].z + vn[k].w * vn[k].w;
            }
            #pragma unroll
            for (int o = 16; o; o >>= 1) {
                s  += __shfl_xor_sync(0xffffffffu, s, o);
                ss += __shfl_xor_sync(0xffffffffu, ss, o);
            }
            if (lane == 0) st[1][pair][half] = make_float2(s, ss);
            BAR_SYNC(barid, 64);
            float2 oth = st[1][pair][half ^ 1];
            s += oth.x; ss += oth.y;
            float mu   = s * (1.0f / (float)H_);
            float rstd = rsqrtf(ss * (1.0f / (float)H_) - mu * mu + 1e-5f);
            #pragma unroll
            for (int k = 0; k < 8; k++) {
                acc[k].x += (vn[k].x - mu) * rstd;
                acc[k].y += (vn[k].y - mu) * rstd;
                acc[k].z += (vn[k].z - mu) * rstd;
                acc[k].w += (vn[k].w - mu) * rstd;
            }
        }
    }

    // merge the 4 pairs' accumulators (per column half) in smem
    float* smh = sm + half * 1024;
    for (int p = 0; p < 4; p++) {
        if (pair == p) {
            #pragma unroll
            for (int k = 0; k < 8; k++) {
                float4* d = (float4*)&smh[k * 128 + lane * 4];
                if (p == 0) {
                    *d = acc[k];
                } else {
                    float4 t = *d;
                    t.x += acc[k].x; t.y += acc[k].y;
                    t.z += acc[k].z; t.w += acc[k].w;
                    *d = t;
                }
            }
        }
        __syncthreads();
    }

    float* g = g_acc + b * H_;
    #pragma unroll
    for (int t = 0; t < 8; t++)
        atomicAdd(g + tid * 8 + t, sm[tid * 8 + t]);
}

// ---------------- K2: split-K GEMV, 4 columns per warp ----------------
// 512 blocks: bid<256 -> Wk part (N=16 rows), else Wq part (N=4 rows).
// c==0 chunk-block adds bias (exactly once per output via commutative atomics).
template <int N>
__device__ __forceinline__ void gemv_compute(const float* __restrict__ W,
                                             const float* __restrict__ bias,
                                             float* __restrict__ OUT,
                                             const float4* __restrict__ As4,
                                             int cg, int c, int lane, int w) {
    int j0 = cg * 32 + w * 4;
    float acc[N][4];
    #pragma unroll
    for (int e = 0; e < N; e++)
        #pragma unroll
        for (int jj = 0; jj < 4; jj++) acc[e][jj] = 0.0f;

    const float4* W4 = (const float4*)W;
    #pragma unroll
    for (int t = 0; t < 4; t++) {
        float4 wv[4];
        #pragma unroll
        for (int jj = 0; jj < 4; jj++)
            wv[jj] = W4[(size_t)(j0 + jj) * 512 + c * 128 + t * 32 + lane];
        #pragma unroll
        for (int e = 0; e < N; e++) {
            float4 a = As4[e * 128 + t * 32 + lane];
            #pragma unroll
            for (int jj = 0; jj < 4; jj++) {
                acc[e][jj] = fmaf(a.x, wv[jj].x,
                             fmaf(a.y, wv[jj].y,
                             fmaf(a.z, wv[jj].z,
                             fmaf(a.w, wv[jj].w, acc[e][jj]))));
            }
        }
    }
    #pragma unroll
    for (int e = 0; e < N; e++)
        #pragma unroll
        for (int jj = 0; jj < 4; jj++) {
            float vsum = acc[e][jj];
            #pragma unroll
            for (int o = 16; o; o >>= 1)
                vsum += __shfl_xor_sync(0xffffffffu, vsum, o);
            acc[e][jj] = vsum;
        }
    if (lane == 0) {
        #pragma unroll
        for (int jj = 0; jj < 4; jj++) {
            float bb = (c == 0) ? bias[j0 + jj] : 0.0f;
            #pragma unroll
            for (int e = 0; e < N; e++)
                atomicAdd(&OUT[e * H_ + j0 + jj], acc[e][jj] + bb);
        }
    }
}

__global__ void __launch_bounds__(256) k_gemv(const float* __restrict__ Wq,
                                              const float* __restrict__ bq,
                                              const float* __restrict__ Wk,
                                              const float* __restrict__ bk,
                                              const float* __restrict__ lemb,
                                              const float* __restrict__ cemb,
                                              const float* __restrict__ gamma,
                                              const float* __restrict__ beta,
                                              const int* __restrict__ curp) {
    extern __shared__ float4 As4[];   // [N][128] float4 = N x 512 floats
    int bid = blockIdx.x;
    int tid = threadIdx.x, lane = tid & 31, w = tid >> 5;

    if (bid < 256) {
        int cg = bid >> 2, c = bid & 3;
        const float4* l4 = (const float4*)lemb;
        const float4* c4 = (const float4*)cemb;
        #pragma unroll
        for (int i = tid; i < 16 * 128; i += 256) {
            int e = i >> 7, p = i & 127;
            float4 a = l4[e * 512 + c * 128 + p];
            float4 bb = c4[e * 512 + c * 128 + p];
            a.x += bb.x; a.y += bb.y; a.z += bb.z; a.w += bb.w;
            As4[i] = a;
        }
        __syncthreads();
        gemv_compute<E_>(Wk, bk, g_k, As4, cg, c, lane, w);
    } else {
        bid -= 256;
        int cg = bid >> 2, c = bid & 3;
        int cur = curp ? curp[0] : 0;
        const float4* l4 = (const float4*)lemb + (size_t)cur * 512;
        const float4* g4 = (const float4*)gamma;
        const float4* b4 = (const float4*)beta;
        const float4* a4 = (const float4*)g_acc;
        #pragma unroll
        for (int i = tid; i < 4 * 128; i += 256) {
            int e = i >> 7, p = i & 127;
            int hp = c * 128 + p;
            float4 le = l4[hp], ga = g4[hp], be = b4[hp];
            float4 ac = a4[e * 512 + hp];
            float4 r;
            r.x = le.x + ga.x * (ac.x * (1.0f / (float)S_)) + be.x;
            r.y = le.y + ga.y * (ac.y * (1.0f / (float)S_)) + be.y;
            r.z = le.z + ga.z * (ac.z * (1.0f / (float)S_)) + be.z;
            r.w = le.w + ga.w * (ac.w * (1.0f / (float)S_)) + be.w;
            As4[i] = r;
        }
        __syncthreads();
        gemv_compute<B_>(Wq, bq, g_q, As4, cg, c, lane, w);
    }
}

// ---------------- K3: attention dots + edge bias (spread across SMs) --------
// grid 80: blocks 0..63 -> attention[b][e] (float4 dot, 4 loads/thread);
//          blocks 64..79 -> edge_bias[j] (wsum recomputed inline).
// Blocks 0..7 also zero g_acc for the next call (k_gemv, its only reader,
// completed before this kernel started).
__global__ void __launch_bounds__(256) k_att(const float* __restrict__ edge,
                                             const int* __restrict__ curp,
                                             const int* __restrict__ avail) {
    __shared__ float red[8];
    int bid = blockIdx.x, tid = threadIdx.x;
    int lane = tid & 31, wid = tid >> 5;

    if (bid < 8)
        ((float4*)g_acc)[bid * 256 + tid] = make_float4(0.f, 0.f, 0.f, 0.f);

    float s = 0.0f;
    if (bid < 64) {
        int b = bid >> 4, e = bid & 15;
        const float4* q4 = (const float4*)(g_q + (size_t)b * H_);
        const float4* k4 = (const float4*)(g_k + (size_t)e * H_);
        float4 qa = q4[tid],       ka = k4[tid];
        float4 qb = q4[tid + 256], kb = k4[tid + 256];
        s = qa.x * ka.x + qa.y * ka.y + qa.z * ka.z + qa.w * ka.w
          + qb.x * kb.x + qb.y * kb.y + qb.z * kb.z + qb.w * kb.w;
    } else {
        int j = bid - 64;
        int cur = curp ? curp[0] : 0;
        float wgt[E_];
        #pragma unroll
        for (int i = 0; i < E_; i++) {
            int d = i - cur; if (d < 0) d = -d;
            float wi = 1.0f / (float)(d > 1 ? d : 1);
            wgt[i] = (avail[i] != 0 && i != cur) ? wi : 0.0f;
        }
        for (int hh = tid; hh < ED_; hh += 256) {
            float ws = 0.0f;
            #pragma unroll
            for (int i = 0; i < E_; i++) ws += wgt[i] * edge[i * ED_ + hh];
            s += ws * edge[j * ED_ + hh];
        }
    }
    #pragma unroll
    for (int o = 16; o; o >>= 1) s += __shfl_xor_sync(0xffffffffu, s, o);
    if (lane == 0) red[wid] = s;
    __syncthreads();
    if (tid == 0) {
        float t = 0.0f;
        #pragma unroll
        for (int w = 0; w < 8; w++) t += red[w];
        if (bid < 64) g_att[bid] = t * 0.022097086912079612f;  // 1/sqrt(2048)
        else          g_eb[bid - 64] = t;
    }
}

// ---------------- K4: softmax/KL/argmax + output (pure epilogue) ------------
__global__ void __launch_bounds__(128) k_final(const float* __restrict__ spatial,
                                               const int* __restrict__ curp,
                                               const int* __restrict__ avail,
                                               float* __restrict__ out,
                                               int out_size) {
    int tid = threadIdx.x;
    int lane = tid & 31, w = tid >> 5;
    int cur = curp ? curp[0] : 0;

    __shared__ float sprobs[64];
    __shared__ float klpart[4];
    __shared__ float s_loss;
    __shared__ int   sidx;

    {
        int b = w;
        float navail = 0.0f;
        #pragma unroll
        for (int i = 0; i < E_; i++) navail += (avail[i] != 0) ? 1.0f : 0.0f;
        float t = 1.0f / navail;

        float s = -1e9f;
        if (lane < 16) {
            int e = lane;
            int d = e - cur; if (d < 0) d = -d;
            float sc = g_att[b * E_ + e] + spatial[d] + g_eb[e];
            s = (avail[e] != 0) ? sc : -1e9f;
        }
        float m = s;
        #pragma unroll
        for (int o = 16; o; o >>= 1) m = fmaxf(m, __shfl_xor_sync(0xffffffffu, m, o));
        float ex = (lane < 16) ? expf(s - m) : 0.0f;
        float sum = ex;
        #pragma unroll
        for (int o = 16; o; o >>= 1) sum += __shfl_xor_sync(0xffffffffu, sum, o);
        float prob = (lane < 16) ? ex / sum : 0.0f;
        if (lane < 16) sprobs[b * 16 + lane] = prob;

        float term = (lane < 16) ? t * (logf(t) - logf(fmaxf(prob, 1e-10f))) : 0.0f;
        float ksum = term;
        #pragma unroll
        for (int o = 16; o; o >>= 1) ksum += __shfl_xor_sync(0xffffffffu, ksum, o);
        if (lane == 0) klpart[b] = ksum;

        if (b == 0) {
            float pm = prob;
            #pragma unroll
            for (int o = 16; o; o >>= 1)
                pm = fmaxf(pm, __shfl_xor_sync(0xffffffffu, pm, o));
            unsigned ball = __ballot_sync(0xffffffffu, (lane < 16) && (prob == pm));
            if (lane == 0) sidx = __ffs(ball) - 1;
        }
    }

    __syncthreads();
    if (tid == 0)
        s_loss = (klpart[0] + klpart[1] + klpart[2] + klpart[3]) * 0.25f * 0.01f;
    __syncthreads();

    if (out_size == 64) {
        if (tid < 64) out[tid] = sprobs[tid];
    } else {
        if (tid == 0 && out_size >= 1) out[0] = s_loss;
        if (tid < 64 && 1 + tid < out_size) out[1 + tid] = sprobs[tid];
        if (tid == 0 && out_size >= 66) out[65] = (float)sidx;
        for (int i = 66 + tid; i < out_size; i += 128) out[i] = 0.0f;
    }
}

// ---------------- host ----------------
extern "C" void kernel_launch(void* const* d_in, const int* in_sizes, int n_in,
                              void* d_out, int out_size) {
    const float* hidden  = (const float*)d_in[0];
    const float* lemb    = (const float*)d_in[1];
    const float* cemb    = (const float*)d_in[2];
    const float* spatial = (const float*)d_in[3];
    const float* edge    = (const float*)d_in[4];
    const float* gamma   = (const float*)d_in[5];
    const float* beta    = (const float*)d_in[6];
    const float* Wq      = (const float*)d_in[7];
    const float* bq      = (const float*)d_in[8];
    const float* Wk      = (const float*)d_in[9];
    const float* bk      = (const float*)d_in[10];
    // d_in[11], d_in[12] = Wv, bv : dead in the reference, never touched.

    const int* curp  = nullptr;
    const int* avail = nullptr;
    if (n_in >= 15) {
        curp  = (const int*)d_in[13];
        avail = (const int*)d_in[14];
    } else {
        avail = (const int*)d_in[n_in - 1];
    }

    k_ln_mean<<<256, 256>>>(hidden);
    k_gemv<<<512, 256, 16 * 512 * sizeof(float)>>>(Wq, bq, Wk, bk, lemb, cemb,
                                                   gamma, beta, curp);
    k_att<<<80, 256>>>(edge, curp, avail);
    k_final<<<1, 128>>>(spatial, curp, avail, (float*)d_out, out_size);
}

// round 13
// speedup vs baseline: 1.2768x; 1.2768x over previous
#include <cuda_runtime.h>
#include <math.h>

#define B_ 4
#define S_ 4096
#define H_ 2048
#define E_ 16
#define ED_ 512

// ---------------- scratch ----------------
__device__ float g_acc[B_ * H_];   // sum_s (x-mu)*rstd
__device__ float g_q[B_ * H_];     // seeded with bq by k_init
__device__ float g_k[E_ * H_];     // seeded with bk by k_init
__device__ float g_att[B_ * E_];
__device__ float g_eb[E_];
__device__ unsigned int g_ctr;     // last-block counter; reset to 0 each call

// ---------------- K0: init (zero g_acc, seed biases) ----------------
// 192*256 = 49152 = 8192 (g_acc) + 32768 (g_k) + 8192 (g_q)
__global__ void k_init(const float* __restrict__ bq, const float* __restrict__ bk) {
    int i = blockIdx.x * 256 + threadIdx.x;
    if (i < B_ * H_) {
        g_acc[i] = 0.0f;
    } else if (i < B_ * H_ + E_ * H_) {
        int j = i - B_ * H_;
        g_k[j] = bk[j & (H_ - 1)];
    } else {
        int j = i - B_ * H_ - E_ * H_;
        g_q[j] = bq[j & (H_ - 1)];
    }
}

// ---------------- K1: fused LayerNorm + mean over S ----------------
// grid 256 = 4 batches * 64 blocks; 256 threads = 8 warps = 4 warp-pairs.
// A warp-pair owns a row: each warp covers 1024 columns (8 float4/lane).
// Next-row prefetch overlaps the current row's reduction; pair stats joined
// via a double-buffered smem exchange + block barrier (proven fastest config).
__global__ void __launch_bounds__(256, 2) k_ln_mean(const float* __restrict__ x) {
    int b   = blockIdx.x >> 6;      // 64 blocks per batch
    int blk = blockIdx.x & 63;
    int tid = threadIdx.x;
    int lane = tid & 31, wid = tid >> 5;
    int pair = wid >> 1, half = wid & 1;

    int row0 = blk * 64 + pair * 16;    // this pair's first row
    const float* xb = x + ((size_t)b * S_ + row0) * H_ + half * 1024;

    __shared__ float2 st[2][4][2];      // [buf][pair][half]
    __shared__ float sm[H_];

    float4 v[8], vn[8], acc[8];
    #pragma unroll
    for (int k = 0; k < 8; k++) acc[k] = make_float4(0.f, 0.f, 0.f, 0.f);

    {
        const float4* row = (const float4*)xb;
        #pragma unroll
        for (int k = 0; k < 8; k++) v[k] = __ldcs(&row[k * 32 + lane]);
    }

    for (int r = 0; r < 16; r++) {
        if (r < 15) {
            const float4* nr = (const float4*)(xb + (size_t)(r + 1) * H_);
            #pragma unroll
            for (int k = 0; k < 8; k++) vn[k] = __ldcs(&nr[k * 32 + lane]);
        }
        float s = 0.f, ss = 0.f;
        #pragma unroll
        for (int k = 0; k < 8; k++) {
            s  += v[k].x + v[k].y + v[k].z + v[k].w;
            ss += v[k].x * v[k].x + v[k].y * v[k].y
                + v[k].z * v[k].z + v[k].w * v[k].w;
        }
        #pragma unroll
        for (int o = 16; o; o >>= 1) {
            s  += __shfl_xor_sync(0xffffffffu, s, o);
            ss += __shfl_xor_sync(0xffffffffu, ss, o);
        }
        if (lane == 0) st[r & 1][pair][half] = make_float2(s, ss);
        __syncthreads();
        float2 oth = st[r & 1][pair][half ^ 1];
        s += oth.x; ss += oth.y;

        float mu   = s * (1.0f / (float)H_);
        float var  = ss * (1.0f / (float)H_) - mu * mu;
        float rstd = rsqrtf(var + 1e-5f);
        #pragma unroll
        for (int k = 0; k < 8; k++) {
            acc[k].x += (v[k].x - mu) * rstd;
            acc[k].y += (v[k].y - mu) * rstd;
            acc[k].z += (v[k].z - mu) * rstd;
            acc[k].w += (v[k].w - mu) * rstd;
        }
        #pragma unroll
        for (int k = 0; k < 8; k++) v[k] = vn[k];
    }

    // merge the 4 pairs' accumulators (per column half) in smem
    float* smh = sm + half * 1024;
    for (int p = 0; p < 4; p++) {
        if (pair == p) {
            #pragma unroll
            for (int k = 0; k < 8; k++) {
                float4* d = (float4*)&smh[k * 128 + lane * 4];
                if (p == 0) {
                    *d = acc[k];
                } else {
                    float4 t = *d;
                    t.x += acc[k].x; t.y += acc[k].y;
                    t.z += acc[k].z; t.w += acc[k].w;
                    *d = t;
                }
            }
        }
        __syncthreads();
    }

    float* g = g_acc + b * H_;
    #pragma unroll
    for (int t = 0; t < 8; t++)
        atomicAdd(g + tid * 8 + t, sm[tid * 8 + t]);
}

// ---------------- K2: split-K GEMV, 4 columns per warp ----------------
// 512 blocks: bid<256 -> Wk part (N=16 rows), else Wq part (N=4 rows).
// Per part: 64 col-groups (32 cols each, warp handles 4) x 4 H-chunks of 512.
// A (lf / qin) is computed on the fly during smem staging.
template <int N>
__device__ __forceinline__ void gemv_compute(const float* __restrict__ W,
                                             float* __restrict__ OUT,
                                             const float4* __restrict__ As4,
                                             int cg, int c, int lane, int w) {
    int j0 = cg * 32 + w * 4;
    float acc[N][4];
    #pragma unroll
    for (int e = 0; e < N; e++)
        #pragma unroll
        for (int jj = 0; jj < 4; jj++) acc[e][jj] = 0.0f;

    const float4* W4 = (const float4*)W;
    #pragma unroll
    for (int t = 0; t < 4; t++) {
        float4 wv[4];
        #pragma unroll
        for (int jj = 0; jj < 4; jj++)
            wv[jj] = W4[(size_t)(j0 + jj) * 512 + c * 128 + t * 32 + lane];
        #pragma unroll
        for (int e = 0; e < N; e++) {
            float4 a = As4[e * 128 + t * 32 + lane];
            #pragma unroll
            for (int jj = 0; jj < 4; jj++) {
                acc[e][jj] = fmaf(a.x, wv[jj].x,
                             fmaf(a.y, wv[jj].y,
                             fmaf(a.z, wv[jj].z,
                             fmaf(a.w, wv[jj].w, acc[e][jj]))));
            }
        }
    }
    #pragma unroll
    for (int e = 0; e < N; e++)
        #pragma unroll
        for (int jj = 0; jj < 4; jj++) {
            float vsum = acc[e][jj];
            #pragma unroll
            for (int o = 16; o; o >>= 1)
                vsum += __shfl_xor_sync(0xffffffffu, vsum, o);
            acc[e][jj] = vsum;
        }
    if (lane == 0) {
        #pragma unroll
        for (int e = 0; e < N; e++)
            #pragma unroll
            for (int jj = 0; jj < 4; jj++)
                atomicAdd(&OUT[e * H_ + j0 + jj], acc[e][jj]);
    }
}

__global__ void __launch_bounds__(256) k_gemv(const float* __restrict__ Wq,
                                              const float* __restrict__ Wk,
                                              const float* __restrict__ lemb,
                                              const float* __restrict__ cemb,
                                              const float* __restrict__ gamma,
                                              const float* __restrict__ beta,
                                              const int* __restrict__ curp) {
    extern __shared__ float4 As4[];   // [N][128] float4 = N x 512 floats
    int bid = blockIdx.x;
    int tid = threadIdx.x, lane = tid & 31, w = tid >> 5;

    if (bid < 256) {
        int cg = bid >> 2, c = bid & 3;
        const float4* l4 = (const float4*)lemb;
        const float4* c4 = (const float4*)cemb;
        #pragma unroll
        for (int i = tid; i < 16 * 128; i += 256) {
            int e = i >> 7, p = i & 127;
            float4 a = l4[e * 512 + c * 128 + p];
            float4 bb = c4[e * 512 + c * 128 + p];
            a.x += bb.x; a.y += bb.y; a.z += bb.z; a.w += bb.w;
            As4[i] = a;
        }
        __syncthreads();
        gemv_compute<E_>(Wk, g_k, As4, cg, c, lane, w);
    } else {
        bid -= 256;
        int cg = bid >> 2, c = bid & 3;
        int cur = curp ? curp[0] : 0;
        const float4* l4 = (const float4*)lemb + (size_t)cur * 512;
        const float4* g4 = (const float4*)gamma;
        const float4* b4 = (const float4*)beta;
        const float4* a4 = (const float4*)g_acc;
        #pragma unroll
        for (int i = tid; i < 4 * 128; i += 256) {
            int e = i >> 7, p = i & 127;
            int hp = c * 128 + p;
            float4 le = l4[hp], ga = g4[hp], be = b4[hp];
            float4 ac = a4[e * 512 + hp];
            float4 r;
            r.x = le.x + ga.x * (ac.x * (1.0f / (float)S_)) + be.x;
            r.y = le.y + ga.y * (ac.y * (1.0f / (float)S_)) + be.y;
            r.z = le.z + ga.z * (ac.z * (1.0f / (float)S_)) + be.z;
            r.w = le.w + ga.w * (ac.w * (1.0f / (float)S_)) + be.w;
            As4[i] = r;
        }
        __syncthreads();
        gemv_compute<B_>(Wq, g_q, As4, cg, c, lane, w);
    }
}

// ---------------- K3: attention dots + edge bias + fused epilogue -----------
// grid 80: blocks 0..63 -> attention[b][e] (float4 dots, 4 loads up front);
//          blocks 64..79 -> edge_bias[j] (wsum recomputed inline).
// The LAST block to finish (threadfence + atomic counter) runs the softmax /
// KL / argmax epilogue and writes the output, then resets the counter so the
// kernel is deterministic under graph replay.
__global__ void __launch_bounds__(256) k_att(const float* __restrict__ edge,
                                             const float* __restrict__ spatial,
                                             const int* __restrict__ curp,
                                             const int* __restrict__ avail,
                                             float* __restrict__ out,
                                             int out_size) {
    __shared__ float red[8];
    __shared__ int is_last;
    int bid = blockIdx.x, tid = threadIdx.x;
    int lane = tid & 31, wid = tid >> 5;
    int cur = curp ? curp[0] : 0;

    float s = 0.0f;
    if (bid < 64) {
        int b = bid >> 4, e = bid & 15;
        const float4* q4 = (const float4*)(g_q + (size_t)b * H_);
        const float4* k4 = (const float4*)(g_k + (size_t)e * H_);
        float4 qa = q4[tid],       ka = k4[tid];
        float4 qb = q4[tid + 256], kb = k4[tid + 256];
        s = qa.x * ka.x + qa.y * ka.y + qa.z * ka.z + qa.w * ka.w
          + qb.x * kb.x + qb.y * kb.y + qb.z * kb.z + qb.w * kb.w;
    } else {
        int j = bid - 64;
        float wgt[E_];
        #pragma unroll
        for (int i = 0; i < E_; i++) {
            int d = i - cur; if (d < 0) d = -d;
            float wi = 1.0f / (float)(d > 1 ? d : 1);
            wgt[i] = (avail[i] != 0 && i != cur) ? wi : 0.0f;
        }
        for (int hh = tid; hh < ED_; hh += 256) {
            float ws = 0.0f;
            #pragma unroll
            for (int i = 0; i < E_; i++) ws += wgt[i] * edge[i * ED_ + hh];
            s += ws * edge[j * ED_ + hh];
        }
    }
    #pragma unroll
    for (int o = 16; o; o >>= 1) s += __shfl_xor_sync(0xffffffffu, s, o);
    if (lane == 0) red[wid] = s;
    __syncthreads();
    if (tid == 0) {
        float t = 0.0f;
        #pragma unroll
        for (int w = 0; w < 8; w++) t += red[w];
        if (bid < 64) g_att[bid] = t * 0.022097086912079612f;  // 1/sqrt(2048)
        else          g_eb[bid - 64] = t;
        __threadfence();
        unsigned int old = atomicAdd(&g_ctr, 1u);
        is_last = (old == 79u) ? 1 : 0;
    }
    __syncthreads();
    if (!is_last) return;

    // ---------------- epilogue: softmax / KL / argmax / output ----------------
    __shared__ float sprobs[64];
    __shared__ float klpart[4];
    __shared__ float s_loss;
    __shared__ int   sidx;

    if (wid < B_) {
        int b = wid;
        float navail = 0.0f;
        #pragma unroll
        for (int i = 0; i < E_; i++) navail += (avail[i] != 0) ? 1.0f : 0.0f;
        float t = 1.0f / navail;

        float sc0 = -1e9f;
        if (lane < 16) {
            int e = lane;
            int d = e - cur; if (d < 0) d = -d;
            float sc = g_att[b * E_ + e] + spatial[d] + g_eb[e];
            sc0 = (avail[e] != 0) ? sc : -1e9f;
        }
        float m = sc0;
        #pragma unroll
        for (int o = 16; o; o >>= 1) m = fmaxf(m, __shfl_xor_sync(0xffffffffu, m, o));
        float ex = (lane < 16) ? expf(sc0 - m) : 0.0f;
        float sum = ex;
        #pragma unroll
        for (int o = 16; o; o >>= 1) sum += __shfl_xor_sync(0xffffffffu, sum, o);
        float prob = (lane < 16) ? ex / sum : 0.0f;
        if (lane < 16) sprobs[b * 16 + lane] = prob;

        float term = (lane < 16) ? t * (logf(t) - logf(fmaxf(prob, 1e-10f))) : 0.0f;
        float ksum = term;
        #pragma unroll
        for (int o = 16; o; o >>= 1) ksum += __shfl_xor_sync(0xffffffffu, ksum, o);
        if (lane == 0) klpart[b] = ksum;

        if (b == 0) {
            float pm = prob;
            #pragma unroll
            for (int o = 16; o; o >>= 1)
                pm = fmaxf(pm, __shfl_xor_sync(0xffffffffu, pm, o));
            unsigned ball = __ballot_sync(0xffffffffu, (lane < 16) && (prob == pm));
            if (lane == 0) sidx = __ffs(ball) - 1;
        }
    }
    __syncthreads();
    if (tid == 0) {
        s_loss = (klpart[0] + klpart[1] + klpart[2] + klpart[3]) * 0.25f * 0.01f;
        g_ctr = 0u;   // reset for next call (graph replay determinism)
    }
    __syncthreads();

    if (out_size == 64) {
        if (tid < 64) out[tid] = sprobs[tid];
    } else {
        if (tid == 0 && out_size >= 1) out[0] = s_loss;
        if (tid < 64 && 1 + tid < out_size) out[1 + tid] = sprobs[tid];
        if (tid == 0 && out_size >= 66) out[65] = (float)sidx;
        for (int i = 66 + tid; i < out_size; i += 256) out[i] = 0.0f;
    }
}

// ---------------- host ----------------
extern "C" void kernel_launch(void* const* d_in, const int* in_sizes, int n_in,
                              void* d_out, int out_size) {
    const float* hidden  = (const float*)d_in[0];
    const float* lemb    = (const float*)d_in[1];
    const float* cemb    = (const float*)d_in[2];
    const float* spatial = (const float*)d_in[3];
    const float* edge    = (const float*)d_in[4];
    const float* gamma   = (const float*)d_in[5];
    const float* beta    = (const float*)d_in[6];
    const float* Wq      = (const float*)d_in[7];
    const float* bq      = (const float*)d_in[8];
    const float* Wk      = (const float*)d_in[9];
    const float* bk      = (const float*)d_in[10];
    // d_in[11], d_in[12] = Wv, bv : dead in the reference, never touched.

    const int* curp  = nullptr;
    const int* avail = nullptr;
    if (n_in >= 15) {
        curp  = (const int*)d_in[13];
        avail = (const int*)d_in[14];
    } else {
        avail = (const int*)d_in[n_in - 1];
    }

    k_init<<<192, 256>>>(bq, bk);
    k_ln_mean<<<256, 256>>>(hidden);
    k_gemv<<<512, 256, 16 * 512 * sizeof(float)>>>(Wq, Wk, lemb, cemb,
                                                   gamma, beta, curp);
    k_att<<<80, 256>>>(edge, spatial, curp, avail, (float*)d_out, out_size);
}